// round 6
// baseline (speedup 1.0000x reference)
#include <cuda_runtime.h>
#include <cstdint>

// TaylorExp: x [4,16,4096,16] f32 -> out [4,16,4096,273] f32
// out_row = [1, 0.5*x, vec(x x^T) / (4*sqrt(2))]
//
// R6: R4 (table decode + st.global.cs evict-first stores) plus L2-resident
// input loads via the 256-bit form ptxas requires on sm_103:
// ld.global.nc.L2::evict_last.v4.b64 (32 B/lane, lanes 0-7 per warp).

#define WARPS_PER_BLOCK 8
#define THREADS (WARPS_PER_BLOCK * 32)

static constexpr int TOTAL_ROWS  = 4 * 16 * 4096;   // 262144
static constexpr int GROUPS      = TOTAL_ROWS / 4;  // 65536 (4 rows per warp)
static constexpr int VEC_PER_GRP = 273;             // float4 per group

__device__ __forceinline__ float lds_f32(unsigned addr) {
    float v;
    asm volatile("ld.shared.f32 %0, [%1];" : "=f"(v) : "r"(addr));
    return v;
}

__device__ __forceinline__ void stg_cs_v4(float4* p, float4 v) {
    asm volatile("st.global.cs.v4.f32 [%0], {%1, %2, %3, %4};"
                 :: "l"(p), "f"(v.x), "f"(v.y), "f"(v.z), "f"(v.w)
                 : "memory");
}

__global__ __launch_bounds__(THREADS)
void TaylorExp_14783277432863_kernel(const float* __restrict__ x,
                                     float* __restrict__ out) {
    __shared__ uint4 tab[273];                     // 4368 B, block-shared
    __shared__ float pq[WARPS_PER_BLOCK][136];     // P[68] | Q[68] per warp

    const int tid  = threadIdx.x;
    const int warp = tid >> 5;
    const int lane = tid & 31;
    const int group = blockIdx.x * WARPS_PER_BLOCK + warp;   // grid exact

    // ---- build offset table (identical for all groups) ----
    for (int k = tid; k < 273; k += THREADS) {
        unsigned w[4];
        #pragma unroll
        for (int c = 0; c < 4; ++c) {
            const int ec  = 4 * k + c;
            const int row = (ec >= 273) + (ec >= 546) + (ec >= 819);
            const int f   = ec - row * 273;
            int ia, ib;                 // float indices into pq[warp][136]
            if (f == 0)       { ia = row * 17;          ib = 68 + row * 17; }
            else if (f <= 16) { ia = row * 17 + f;      ib = 68 + row * 17; }
            else {
                const int q = f - 17;
                ia = row * 17 + 1 + (q >> 4);
                ib = 68 + row * 17 + 1 + (q & 15);
            }
            w[c] = (unsigned)(ia * 4) | ((unsigned)(ib * 4) << 16);  // byte offs
        }
        tab[k] = make_uint4(w[0], w[1], w[2], w[3]);
    }

    // ---- fill per-warp P/Q (pre-scaled inputs) ----
    // Lanes 0-7 each load 32 bytes (8 floats = half a row) with the
    // 256-bit evict_last form. group base = 256B aligned, lane*32 -> 32B ok.
    if (lane < 8) {
        const char* gp = reinterpret_cast<const char*>(x) +
                         (size_t)group * 256 + (size_t)lane * 32;
        unsigned long long d0, d1, d2, d3;
        asm volatile("ld.global.nc.L2::evict_last.v4.b64 {%0, %1, %2, %3}, [%4];"
                     : "=l"(d0), "=l"(d1), "=l"(d2), "=l"(d3) : "l"(gp));
        float f[8];
        f[0] = __uint_as_float((unsigned)(d0 & 0xFFFFFFFFull));
        f[1] = __uint_as_float((unsigned)(d0 >> 32));
        f[2] = __uint_as_float((unsigned)(d1 & 0xFFFFFFFFull));
        f[3] = __uint_as_float((unsigned)(d1 >> 32));
        f[4] = __uint_as_float((unsigned)(d2 & 0xFFFFFFFFull));
        f[5] = __uint_as_float((unsigned)(d2 >> 32));
        f[6] = __uint_as_float((unsigned)(d3 & 0xFFFFFFFFull));
        f[7] = __uint_as_float((unsigned)(d3 >> 32));

        const int row  = lane >> 1;          // 0..3
        const int half = lane & 1;           // 0: cols 0-7, 1: cols 8-15
        float* P = pq[warp];
        float* Q = pq[warp] + 68;
        const int bi = row * 17 + 1 + half * 8;
        const float c2 = 0.5f * 0.70710678118654752f;
        #pragma unroll
        for (int i = 0; i < 8; ++i) {
            P[bi + i] = 0.5f * f[i];
            Q[bi + i] = c2   * f[i];
        }
    }
    if (lane < 4) {                          // unit entries for const/linear
        pq[warp][lane * 17]      = 1.0f;
        pq[warp][68 + lane * 17] = 1.0f;
    }
    __syncthreads();

    const unsigned sb = (unsigned)__cvta_generic_to_shared(&pq[warp][0]);
    float4* og = reinterpret_cast<float4*>(out) + (size_t)group * VEC_PER_GRP;

    #pragma unroll
    for (int it = 0; it < 9; ++it) {
        const int k = lane + it * 32;
        if (it < 8 || k < VEC_PER_GRP) {     // 273 = 8*32 + 17
            const uint4 cd = tab[k];
            float4 v;
            v.x = lds_f32(sb + (cd.x & 0xFFFFu)) * lds_f32(sb + (cd.x >> 16));
            v.y = lds_f32(sb + (cd.y & 0xFFFFu)) * lds_f32(sb + (cd.y >> 16));
            v.z = lds_f32(sb + (cd.z & 0xFFFFu)) * lds_f32(sb + (cd.z >> 16));
            v.w = lds_f32(sb + (cd.w & 0xFFFFu)) * lds_f32(sb + (cd.w >> 16));
            stg_cs_v4(og + k, v);            // evict-first streaming store
        }
    }
}

extern "C" void kernel_launch(void* const* d_in, const int* in_sizes, int n_in,
                              void* d_out, int out_size) {
    const float* x = (const float*)d_in[0];
    float* out = (float*)d_out;
    (void)in_sizes; (void)n_in; (void)out_size;

    const int blocks = GROUPS / WARPS_PER_BLOCK;   // 8192
    TaylorExp_14783277432863_kernel<<<blocks, THREADS>>>(x, out);
}